// round 16
// baseline (speedup 1.0000x reference)
#include <cuda_runtime.h>

#define D     4096
#define TPB   256
#define NWARP (TPB / 32)

// Forced re-read (asm volatile so the compiler cannot CSE it with the pass-1
// loads and keep 16 registers alive across barriers).
__device__ __forceinline__ float4 reload4(const float4* p) {
    float4 v;
    asm volatile("ld.global.ca.v4.f32 {%0,%1,%2,%3}, [%4];"
                 : "=f"(v.x), "=f"(v.y), "=f"(v.z), "=f"(v.w)
                 : "l"(p));
    return v;
}

// Exact top-2 merge of two (hi,lo) pairs (handles duplicates correctly).
__device__ __forceinline__ void merge2(float h2, float l2, float& hi, float& lo) {
    float nh = fmaxf(hi, h2);
    lo = fmaxf(fminf(hi, h2), fmaxf(lo, l2));
    hi = nh;
}

// Tree top-2 fold of 16 row values (4 float4), short critical path.
__device__ __forceinline__ void fold_row(const float4* __restrict__ Xv, int tid,
                                         float& hi, float& lo) {
    float4 f0 = Xv[tid];
    float4 f1 = Xv[TPB + tid];
    float4 f2 = Xv[2 * TPB + tid];
    float4 f3 = Xv[3 * TPB + tid];

    float h0a = fmaxf(f0.x, f0.y), l0a = fminf(f0.x, f0.y);
    float h0b = fmaxf(f0.z, f0.w), l0b = fminf(f0.z, f0.w);
    float h0 = fmaxf(h0a, h0b), l0 = fmaxf(fminf(h0a, h0b), fmaxf(l0a, l0b));

    float h1a = fmaxf(f1.x, f1.y), l1a = fminf(f1.x, f1.y);
    float h1b = fmaxf(f1.z, f1.w), l1b = fminf(f1.z, f1.w);
    float h1 = fmaxf(h1a, h1b), l1 = fmaxf(fminf(h1a, h1b), fmaxf(l1a, l1b));

    float h2a = fmaxf(f2.x, f2.y), l2a = fminf(f2.x, f2.y);
    float h2b = fmaxf(f2.z, f2.w), l2b = fminf(f2.z, f2.w);
    float h2 = fmaxf(h2a, h2b), l2 = fmaxf(fminf(h2a, h2b), fmaxf(l2a, l2b));

    float h3a = fmaxf(f3.x, f3.y), l3a = fminf(f3.x, f3.y);
    float h3b = fmaxf(f3.z, f3.w), l3b = fminf(f3.z, f3.w);
    float h3 = fmaxf(h3a, h3b), l3 = fmaxf(fminf(h3a, h3b), fmaxf(l3a, l3b));

    merge2(h1, l1, h0, l0);
    merge2(h3, l3, h2, l2);
    merge2(h2, l2, h0, l0);
    hi = h0; lo = l0;
}

// 50-step bisection, fp32 op-for-op identical to the reference trajectory
// (see earlier rounds for the count>=2 / powf-edge argument). Single-row
// general version, used only when H - L >= 0.998 (powf edge reachable).
__device__ __forceinline__ float bisect_t(float Hraw, float Lraw) {
    const float H = __fmul_rn(0.5f, Hraw);
    const float L = __fmul_rn(0.5f, Lraw);
    const float p = (float)(1.0 / 4095.0);
    float t_min = H - 1.0f;
    float t_max = H - 0.015625f;
    float diff  = t_max - t_min;
    float t     = t_min;
    #pragma unroll 1
    for (int it = 0; it < 50; it++) {
        diff *= 0.5f;
        t = t_min + diff;
        if (t == t_min) break;
        bool mask;
        if (t < L) {
            mask = true;
        } else {
            float u1 = H - t;
            mask = (u1 >= 0.999f) ? (powf(u1, p) >= 1.0f) : false;
        }
        if (mask) t_min = t;
    }
    return t;
}

__global__ __launch_bounds__(TPB, 7)
void entmax_bisect_kernel(const float* __restrict__ X, float* __restrict__ Y) {
    const int tid  = threadIdx.x;
    const int lane = tid & 31;
    const int wid  = tid >> 5;
    const size_t base0 = (size_t)(blockIdx.x * 2) * D;
    const size_t base1 = base0 + D;

    __shared__ float s_h0[NWARP], s_l0[NWARP], s_h1[NWARP], s_l1[NWARP];
    __shared__ float s_t0, s_t1;
    __shared__ float s_S0, s_S1;

    const float4* Xv0 = reinterpret_cast<const float4*>(X + base0);
    const float4* Xv1 = reinterpret_cast<const float4*>(X + base1);
    float4*       Yv0 = reinterpret_cast<float4*>(Y + base0);
    float4*       Yv1 = reinterpret_cast<float4*>(Y + base1);

    if (tid == 0) { s_S0 = 0.0f; s_S1 = 0.0f; }

    // ---- Pass 1: fold both rows (sequential batches keep regs low) ----
    float hi0, lo0, hi1, lo1;
    fold_row(Xv0, tid, hi0, lo0);
    fold_row(Xv1, tid, hi1, lo1);
    const float thi0 = hi0, thi1 = hi1;

    // ---- Interleaved warp butterfly top-2 for both rows (ILP) ----
    #pragma unroll
    for (int off = 16; off > 0; off >>= 1) {
        float oh0 = __shfl_xor_sync(0xffffffffu, hi0, off);
        float ol0 = __shfl_xor_sync(0xffffffffu, lo0, off);
        float oh1 = __shfl_xor_sync(0xffffffffu, hi1, off);
        float ol1 = __shfl_xor_sync(0xffffffffu, lo1, off);
        float nh0 = fmaxf(hi0, oh0);
        lo0 = fmaxf(fmaxf(lo0, ol0), fminf(hi0, oh0));
        hi0 = nh0;
        float nh1 = fmaxf(hi1, oh1);
        lo1 = fmaxf(fmaxf(lo1, ol1), fminf(hi1, oh1));
        hi1 = nh1;
    }

    // ---- Warp-local sure-cold (per row): warp top-2 <= row top-2, so
    // thr_w = min(l_w/2, h_w/2 - 1/64) - 2e-5 <= t_final. Below it ->
    // provably all-zero output; store zeros NOW, pre-barrier. ----
    const float myXs0 = __fmul_rn(0.5f, thi0);
    const float myXs1 = __fmul_rn(0.5f, thi1);
    const float thr0 = fminf(__fmul_rn(0.5f, lo0),
                             __fmul_rn(0.5f, hi0) - 0.015625f) - 2e-5f;
    const float thr1 = fminf(__fmul_rn(0.5f, lo1),
                             __fmul_rn(0.5f, hi1) - 0.015625f) - 2e-5f;
    const bool ec0 = (myXs0 < thr0);
    const bool ec1 = (myXs1 < thr1);

    const float4 zero4 = make_float4(0.0f, 0.0f, 0.0f, 0.0f);
    if (ec0) {
        __stcs(Yv0 + tid,           zero4);
        __stcs(Yv0 + TPB + tid,     zero4);
        __stcs(Yv0 + 2 * TPB + tid, zero4);
        __stcs(Yv0 + 3 * TPB + tid, zero4);
    }
    if (ec1) {
        __stcs(Yv1 + tid,           zero4);
        __stcs(Yv1 + TPB + tid,     zero4);
        __stcs(Yv1 + 2 * TPB + tid, zero4);
        __stcs(Yv1 + 3 * TPB + tid, zero4);
    }

    if (lane == 0) {
        s_h0[wid] = hi0; s_l0[wid] = lo0;
        s_h1[wid] = hi1; s_l1[wid] = lo1;
    }
    __syncthreads();                                      // b1

    // ---- Thread 0: combine 8 warps (tree) for both rows + DUAL bisection ----
    if (tid == 0) {
        float Ha = s_h0[0], La = s_l0[0];
        float Hc = s_h1[0], Lc = s_l1[0];
        {
            float a1h = s_h0[1], a1l = s_l0[1], a2h = s_h0[2], a2l = s_l0[2];
            float a3h = s_h0[3], a3l = s_l0[3], a4h = s_h0[4], a4l = s_l0[4];
            float a5h = s_h0[5], a5l = s_l0[5], a6h = s_h0[6], a6l = s_l0[6];
            float a7h = s_h0[7], a7l = s_l0[7];
            merge2(a1h, a1l, Ha, La);
            merge2(a3h, a3l, a2h, a2l);
            merge2(a5h, a5l, a4h, a4l);
            merge2(a7h, a7l, a6h, a6l);
            merge2(a2h, a2l, Ha, La);
            merge2(a6h, a6l, a4h, a4l);
            merge2(a4h, a4l, Ha, La);
        }
        {
            float c1h = s_h1[1], c1l = s_l1[1], c2h = s_h1[2], c2l = s_l1[2];
            float c3h = s_h1[3], c3l = s_l1[3], c4h = s_h1[4], c4l = s_l1[4];
            float c5h = s_h1[5], c5l = s_l1[5], c6h = s_h1[6], c6l = s_l1[6];
            float c7h = s_h1[7], c7l = s_l1[7];
            merge2(c1h, c1l, Hc, Lc);
            merge2(c3h, c3l, c2h, c2l);
            merge2(c5h, c5l, c4h, c4l);
            merge2(c7h, c7l, c6h, c6l);
            merge2(c2h, c2l, Hc, Lc);
            merge2(c6h, c6l, c4h, c4l);
            merge2(c4h, c4l, Hc, Lc);
        }

        const float H0s = __fmul_rn(0.5f, Ha), L0s = __fmul_rn(0.5f, La);
        const float H1s = __fmul_rn(0.5f, Hc), L1s = __fmul_rn(0.5f, Lc);

        if (H0s - L0s < 0.998f && H1s - L1s < 0.998f) {
            // Dual branchless bisection: two independent chains dual-issue.
            // Frozen rows (t==t_min) self-noop: assigning t==t_min changes
            // nothing, so no per-row freeze flag is needed.
            float t0m = H0s - 1.0f, t1m = H1s - 1.0f;
            float d0 = (H0s - 0.015625f) - t0m;
            float d1 = (H1s - 0.015625f) - t1m;
            float t0 = t0m, t1 = t1m;
            #pragma unroll 1
            for (int it = 0; it < 50; it++) {
                d0 *= 0.5f;            t0 = t0m + d0;
                d1 *= 0.5f;            t1 = t1m + d1;
                if (t0 == t0m && t1 == t1m) break;   // both frozen
                t0m = (t0 < L0s) ? t0 : t0m;
                t1m = (t1 < L1s) ? t1 : t1m;
            }
            s_t0 = t0; s_t1 = t1;
        } else {
            s_t0 = bisect_t(Ha, La);
            s_t1 = bisect_t(Hc, Lc);
        }
    }
    __syncthreads();                                      // b2

    const float t0 = s_t0, t1 = s_t1;
    const float p = (float)(1.0 / 4095.0);
    const bool hot0 = (myXs0 > t0);                       // ec0 => never hot
    const bool hot1 = (myXs1 > t1);

    // ---- Pass 2 (hot threads, ~1-3 per row): re-read, atomic-add z sums ----
    if (hot0) {
        float sum = 0.0f;
        #pragma unroll
        for (int k = 0; k < 4; k++) {
            float4 g = reload4(Xv0 + k * TPB + tid);
            float u;
            u = __fmul_rn(0.5f, g.x) - t0; if (u > 0.0f) sum += powf(u, p);
            u = __fmul_rn(0.5f, g.y) - t0; if (u > 0.0f) sum += powf(u, p);
            u = __fmul_rn(0.5f, g.z) - t0; if (u > 0.0f) sum += powf(u, p);
            u = __fmul_rn(0.5f, g.w) - t0; if (u > 0.0f) sum += powf(u, p);
        }
        atomicAdd(&s_S0, sum);
    }
    if (hot1) {
        float sum = 0.0f;
        #pragma unroll
        for (int k = 0; k < 4; k++) {
            float4 g = reload4(Xv1 + k * TPB + tid);
            float u;
            u = __fmul_rn(0.5f, g.x) - t1; if (u > 0.0f) sum += powf(u, p);
            u = __fmul_rn(0.5f, g.y) - t1; if (u > 0.0f) sum += powf(u, p);
            u = __fmul_rn(0.5f, g.z) - t1; if (u > 0.0f) sum += powf(u, p);
            u = __fmul_rn(0.5f, g.w) - t1; if (u > 0.0f) sum += powf(u, p);
        }
        atomicAdd(&s_S1, sum);
    }
    __syncthreads();                                      // b3

    const float S0 = s_S0, S1 = s_S1;

    // ---- Epilogue: hot threads write spans; deferred-cold write zeros ----
    if (hot0) {
        const float rinv = 1.0f / S0;
        #pragma unroll
        for (int k = 0; k < 4; k++) {
            float4 g = reload4(Xv0 + k * TPB + tid);
            float4 o = zero4;
            float u;
            u = __fmul_rn(0.5f, g.x) - t0; if (u > 0.0f) o.x = powf(u, p) * rinv;
            u = __fmul_rn(0.5f, g.y) - t0; if (u > 0.0f) o.y = powf(u, p) * rinv;
            u = __fmul_rn(0.5f, g.z) - t0; if (u > 0.0f) o.z = powf(u, p) * rinv;
            u = __fmul_rn(0.5f, g.w) - t0; if (u > 0.0f) o.w = powf(u, p) * rinv;
            __stcs(Yv0 + k * TPB + tid, o);
        }
    } else if (!ec0) {
        __stcs(Yv0 + tid,           zero4);
        __stcs(Yv0 + TPB + tid,     zero4);
        __stcs(Yv0 + 2 * TPB + tid, zero4);
        __stcs(Yv0 + 3 * TPB + tid, zero4);
    }
    if (hot1) {
        const float rinv = 1.0f / S1;
        #pragma unroll
        for (int k = 0; k < 4; k++) {
            float4 g = reload4(Xv1 + k * TPB + tid);
            float4 o = zero4;
            float u;
            u = __fmul_rn(0.5f, g.x) - t1; if (u > 0.0f) o.x = powf(u, p) * rinv;
            u = __fmul_rn(0.5f, g.y) - t1; if (u > 0.0f) o.y = powf(u, p) * rinv;
            u = __fmul_rn(0.5f, g.z) - t1; if (u > 0.0f) o.z = powf(u, p) * rinv;
            u = __fmul_rn(0.5f, g.w) - t1; if (u > 0.0f) o.w = powf(u, p) * rinv;
            __stcs(Yv1 + k * TPB + tid, o);
        }
    } else if (!ec1) {
        __stcs(Yv1 + tid,           zero4);
        __stcs(Yv1 + TPB + tid,     zero4);
        __stcs(Yv1 + 2 * TPB + tid, zero4);
        __stcs(Yv1 + 3 * TPB + tid, zero4);
    }
}

extern "C" void kernel_launch(void* const* d_in, const int* in_sizes, int n_in,
                              void* d_out, int out_size) {
    const float* X = (const float*)d_in[0];
    float* Y = (float*)d_out;
    const int rows = in_sizes[0] / D;                     // 16384
    entmax_bisect_kernel<<<rows / 2, TPB>>>(X, Y);
}